// round 15
// baseline (speedup 1.0000x reference)
#include <cuda_runtime.h>
#include <cuda_fp16.h>
#include <cstdint>

// Problem constants
#define BB  32
#define TT  256
#define DD  512
#define MPP 20

constexpr int TM     = 64;             // CTA t rows
constexpr int TN     = 32;             // s cols per verified chunk
constexpr int NCHK   = TT / TN;        // 8 s-chunks
constexpr int NM     = 5;              // m-planes per CTA (20 = 4 groups of 5)
constexpr int KC     = 64;             // k per pipeline stage (4 x k16)
constexpr int NST    = DD / KC;        // 8 stages
constexpr int STAGES = 2;              // buffer ring depth (produce-ahead 1)
constexpr int NTHR   = 128;            // 4 warps -> one per SMSP
constexpr int ROWA   = 272;            // A row bytes (f32): 256B data + 16B pad
constexpr int ROWBF  = 256;            // B row bytes (f32): unpadded, XOR-swizzled
constexpr int A_BYTES   = TM * ROWA;              // 17408
constexpr int B_BYTES   = TN * ROWBF;             // 8192
constexpr int STG_BYTES = A_BYTES + B_BYTES;      // 25600

constexpr int S_KMS  = 0;              // 5*512 halves = 5120 B
constexpr int S_MBAR = 5120;           // 4 x 8B mbarriers (2 full + 2 empty)
constexpr int S_BUF  = 5184;           // 64B aligned
constexpr int S_TOTAL = S_BUF + STAGES * STG_BYTES;  // 56384 B (x4 CTAs fits)

constexpr float THRESH = 10.0f;        // tanh(10) = 1 - 4.1e-9; monotone-safe exit

static __device__ __forceinline__ uint32_t s2u(const void* p) {
    return (uint32_t)__cvta_generic_to_shared(p);
}

#define CP16(dst, src) \
    asm volatile("cp.async.cg.shared.global [%0], [%1], 16;" :: "r"(dst), "l"(src))

#define MMA16816(d0, d1, a0, a1, a2, a3, b0, b1)                                  \
    asm volatile("mma.sync.aligned.m16n8k16.row.col.f16.f16.f16.f16 "             \
                 "{%0,%1},{%2,%3,%4,%5},{%6,%7},{%0,%1};"                         \
                 : "+r"(d0), "+r"(d1)                                             \
                 : "r"(a0), "r"(a1), "r"(a2), "r"(a3), "r"(b0), "r"(b1))

// spin (with suspend hint) until the mbarrier phase with given parity completes
#define MBWAIT(addr, ph)                                                          \
    asm volatile("{\n\t.reg .pred P;\n\t"                                         \
                 "MBW%=:\n\t"                                                     \
                 "mbarrier.try_wait.parity.shared.b64 P, [%0], %1, 0x989680;\n\t" \
                 "@!P bra MBW%=;\n\t}"                                            \
                 :: "r"(addr), "r"(ph) : "memory")

static __device__ __forceinline__ uint32_t hmul2u(uint32_t a, uint32_t b) {
    __half2 r = __hmul2(*reinterpret_cast<__half2*>(&a),
                        *reinterpret_cast<__half2*>(&b));
    return *reinterpret_cast<uint32_t*>(&r);
}
static __device__ __forceinline__ uint32_t f2h2(float lo, float hi) {
    __half2 h = __floats2half2_rn(lo, hi);
    return *reinterpret_cast<uint32_t*>(&h);
}

// ---------------------------------------------------------------------------
// Single fused kernel: one CTA = (b, t-tile 64, 5 m-planes), 128 threads,
// 4 CTAs/SM. Both A (lt) and B (rt) staged as raw f32 straight from the
// inputs via cp.async; fragments converted to f16 in registers. All 8
// s-chunks share ONE pipelined path; monotone-safe early exit after any
// chunk where every row's running max clears THRESH (exact otherwise).
// ---------------------------------------------------------------------------
__global__ __launch_bounds__(NTHR, 4)
void match_kernel(const float* __restrict__ kw, const float* __restrict__ ltf,
                  const float* __restrict__ rtf, float* __restrict__ out) {
    extern __shared__ __align__(128) char smem[];
    const int tid = threadIdx.x;
    const int b   = blockIdx.z;
    const int m0  = blockIdx.y * NM;
    const int t0  = blockIdx.x * TM;
    const uint32_t sbase   = s2u(smem);
    const uint32_t sbuf    = sbase + S_BUF;
    const uint32_t mbfull  = sbase + S_MBAR;        // 2 x 8B
    const uint32_t mbempty = sbase + S_MBAR + 16;   // 2 x 8B

    if (tid == 0) {
#pragma unroll
        for (int i = 0; i < STAGES; i++) {
            asm volatile("mbarrier.init.shared.b64 [%0], %1;"
                         :: "r"(mbfull + 8 * i), "r"((uint32_t)NTHR) : "memory");
            asm volatile("mbarrier.init.shared.b64 [%0], %1;"
                         :: "r"(mbempty + 8 * i), "r"(4u) : "memory");
        }
    }

    // stage km rows (m0..m0+4) as fp16
    __half* kms = reinterpret_cast<__half*>(smem + S_KMS);
#pragma unroll
    for (int e = tid; e < NM * DD; e += NTHR) {
        int mi = e >> 9, c = e & (DD - 1);
        kms[e] = __float2half_rn(kw[(m0 + mi) * DD + c]);
    }
    __syncthreads();   // mbarrier init + kms visible

    const float* ltb  = ltf + (size_t)(b * TT + t0) * DD;
    const float* rtfb = rtf + (size_t)b * TT * DD;

    const int wid  = tid >> 5;    // warp = 16 t-rows (4 warps x 16 = 64)
    const int lane = tid & 31;
    const int wt   = wid;         // 0..3
    const int g    = lane >> 2;   // 0..7
    const int q    = lane & 3;    // 0..3

    // A fragment f32 base: row wt*16+g, byte col 8q (k=2q)
    const uint32_t a00 = (uint32_t)(wt * 16 + g) * ROWA + (uint32_t)(8 * q);
    const int c0 = q * 2;
    // B swizzle helpers
    const int qh = q >> 1;          // chunk sub-offset
    const int qw = (q & 1) << 3;    // byte within chunk
    const int gx = g << 1;          // XOR key

    float runmax[NM][2];
#pragma unroll
    for (int mi = 0; mi < NM; mi++) { runmax[mi][0] = -3.4e38f; runmax[mi][1] = -3.4e38f; }

    int fullp[STAGES]  = {0, 0};
    int emptyp[STAGES] = {1, 1};

    auto produce = [&](int st, int chunk) {
        const int bfi = st & 1;
        const uint32_t sb = sbuf + bfi * STG_BYTES;
        MBWAIT(mbempty + 8 * bfi, emptyp[bfi]);
        emptyp[bfi] ^= 1;
        const int k0 = st * KC;
#pragma unroll
        for (int i = 0; i < 8; i++) {   // A: 64 rows x 16 x 16B f32 chunks
            int c = tid + i * NTHR, row = c >> 4, sub = c & 15;
            CP16(sb + row * ROWA + sub * 16, ltb + row * DD + k0 + sub * 4);
        }
#pragma unroll
        for (int i = 0; i < 4; i++) {   // B: 32 rows x 16 x 16B f32 chunks, swizzled
            int c = tid + i * NTHR, row = c >> 4, sub = c & 15;
            int sw = sub ^ ((row & 7) << 1);
            CP16(sb + A_BYTES + row * ROWBF + sw * 16,
                 rtfb + (size_t)(chunk * TN + row) * DD + k0 + sub * 4);
        }
        asm volatile("cp.async.mbarrier.arrive.noinc.shared.b64 [%0];"
                     :: "r"(mbfull + 8 * bfi) : "memory");
    };

    // A fragment: 4 float2 LDS + cvt
    auto ldfragA = [&](const char* sp, int kk, uint32_t* af) {
        const char* p0 = sp + a00 + kk * 64;
        float2 f0 = *reinterpret_cast<const float2*>(p0);
        float2 f1 = *reinterpret_cast<const float2*>(p0 + 8 * ROWA);
        float2 f2 = *reinterpret_cast<const float2*>(p0 + 32);
        float2 f3 = *reinterpret_cast<const float2*>(p0 + 8 * ROWA + 32);
        af[0] = f2h2(f0.x, f0.y);
        af[1] = f2h2(f1.x, f1.y);
        af[2] = f2h2(f2.x, f2.y);
        af[3] = f2h2(f3.x, f3.y);
    };
    // B fragment: per ni, two float2 LDS (k-lo, k-hi) from swizzled f32 tile
    auto ldfragB = [&](const char* sp, int kk, uint32_t* bf) {
        const char* bp = sp + A_BYTES;
        const int cl = kk * 4 + qh;       // k-lo chunk index
#pragma unroll
        for (int ni = 0; ni < 4; ni++) {
            int row = ni * 8 + g;
            const char* rb = bp + row * ROWBF;
            float2 lo = *reinterpret_cast<const float2*>(rb + ((cl ^ gx) << 4) + qw);
            float2 hi = *reinterpret_cast<const float2*>(rb + (((cl + 2) ^ gx) << 4) + qw);
            bf[ni * 2]     = f2h2(lo.x, lo.y);
            bf[ni * 2 + 1] = f2h2(hi.x, hi.y);
        }
    };

    uint32_t acc[NM][4][2];
    auto clear_acc = [&]() {
#pragma unroll
        for (int mi = 0; mi < NM; mi++)
#pragma unroll
            for (int ni = 0; ni < 4; ni++) { acc[mi][ni][0] = 0u; acc[mi][ni][1] = 0u; }
    };

    auto compute = [&](int bfi, int ki) {
        const char* sp = smem + S_BUF + bfi * STG_BYTES;
        uint32_t bfA[8], afA[4], bfB[8], afB[4];
        ldfragB(sp, 0, bfA);
        ldfragA(sp, 0, afA);
#pragma unroll
        for (int kk = 0; kk < 4; kk++) {
            uint32_t* bf = (kk & 1) ? bfB : bfA;
            uint32_t* af = (kk & 1) ? afB : afA;
            if (kk < 3) {
                ldfragB(sp, kk + 1, (kk & 1) ? bfA : bfB);
                ldfragA(sp, kk + 1, (kk & 1) ? afA : afB);
            }
            const int kb = ki * KC + kk * 16;
#pragma unroll
            for (int mi = 0; mi < NM; mi++) {
                const uint32_t kp0 =
                    *reinterpret_cast<const uint32_t*>(&kms[mi * DD + kb + c0]);
                const uint32_t kp1 =
                    *reinterpret_cast<const uint32_t*>(&kms[mi * DD + kb + c0 + 8]);
                uint32_t a0 = hmul2u(af[0], kp0);
                uint32_t a1 = hmul2u(af[1], kp0);
                uint32_t a2 = hmul2u(af[2], kp1);
                uint32_t a3 = hmul2u(af[3], kp1);
#pragma unroll
                for (int ni = 0; ni < 4; ni++)
                    MMA16816(acc[mi][ni][0], acc[mi][ni][1],
                             a0, a1, a2, a3, bf[ni * 2], bf[ni * 2 + 1]);
            }
        }
    };

    // returns true if every row's running max clears THRESH (monotone-safe)
    auto reduce_vote = [&]() -> int {
        bool pred = true;
#pragma unroll
        for (int mi = 0; mi < NM; mi++)
#pragma unroll
            for (int h = 0; h < 2; h++) {
                __half2 v = *reinterpret_cast<__half2*>(&acc[mi][0][h]);
#pragma unroll
                for (int ni = 1; ni < 4; ni++)
                    v = __hmax2(v, *reinterpret_cast<__half2*>(&acc[mi][ni][h]));
                float fm = fmaxf(__low2float(v), __high2float(v));
                fm = fmaxf(fm, __shfl_xor_sync(0xffffffffu, fm, 1));
                fm = fmaxf(fm, __shfl_xor_sync(0xffffffffu, fm, 2));
                runmax[mi][h] = fmaxf(runmax[mi][h], fm);
                pred = pred && (runmax[mi][h] > THRESH);
            }
        return __syncthreads_and((int)pred);
    };

    // ---- unified chunk loop: identical pipelined path for all 8 chunks ----
    int done = 0;
    for (int chunk = 0; chunk < NCHK && !done; chunk++) {
        clear_acc();
        produce(0, chunk);
#pragma unroll
        for (int ki = 0; ki < NST; ki++) {
            const int bfi = ki & 1;
            MBWAIT(mbfull + 8 * bfi, fullp[bfi]);
            fullp[bfi] ^= 1;
            if (ki + 1 < NST) produce(ki + 1, chunk);
            compute(bfi, ki);
            __syncwarp();
            if (lane == 0) {
                asm volatile("{\n\t.reg .b64 t;\n\t"
                             "mbarrier.arrive.shared.b64 t, [%0];\n\t}"
                             :: "r"(mbempty + 8 * bfi) : "memory");
            }
        }
        done = reduce_vote();
    }

    // write: each 4-lane group holds maxes for rows wt*16 + h*8 + g
    if (q == 0) {
#pragma unroll
        for (int mi = 0; mi < NM; mi++)
#pragma unroll
            for (int h = 0; h < 2; h++) {
                int row = wt * 16 + h * 8 + g;
                out[(size_t)(b * TT + t0 + row) * MPP + (m0 + mi)] =
                    tanhf(runmax[mi][h]);
            }
    }
}

// ---------------------------------------------------------------------------
// Launch: inputs: reps_lt[B,T,D] f32, reps_rt[B,T,D] f32, kernel[1,1,1,MP,D] f32.
// Output [B,T,MP] f32. Single kernel, no scratch, no pre-conversion.
// ---------------------------------------------------------------------------
extern "C" void kernel_launch(void* const* d_in, const int* in_sizes, int n_in,
                              void* d_out, int out_size) {
    const float* lt = (const float*)d_in[0];
    const float* rt = (const float*)d_in[1];
    const float* kw = (const float*)d_in[2];
    float* out = (float*)d_out;

    cudaFuncSetAttribute(match_kernel,
                         cudaFuncAttributeMaxDynamicSharedMemorySize, S_TOTAL);
    dim3 grid(TT / TM, MPP / NM, BB);  // (4, 4, 32) = 512 CTAs
    match_kernel<<<grid, NTHR, S_TOTAL>>>(kw, lt, rt, out);
}